// round 17
// baseline (speedup 1.0000x reference)
#include <cuda_runtime.h>
#include <cuda_fp16.h>
#include <math.h>
#include <stdint.h>

// Problem constants
#define BSZ 2
#define TLEN 2048
#define CDIM 1024
#define HN 16
#define DH 64
#define MROWS (BSZ * TLEN)   // 4096

// Scratch (allocation-free rule: __device__ globals)
__device__ __half g_qkvh[(size_t)MROWS * 3 * CDIM];   // fp16 qkv [B,T,3C]
__device__ __half g_yh[(size_t)MROWS * CDIM];         // fp16 attention output
__device__ __half g_xh[(size_t)MROWS * CDIM];         // fp16(x)
__device__ __half g_wth[(size_t)4 * CDIM * CDIM];     // fp16(W_attn^T), fp16(W_proj^T)

// ---------------------------------------------------------------------------
// helpers
// ---------------------------------------------------------------------------
__device__ __forceinline__ void mma_f16(float* d, const uint32_t* a, const uint32_t* b) {
    asm volatile(
        "mma.sync.aligned.m16n8k16.row.col.f32.f16.f16.f32 "
        "{%0,%1,%2,%3}, {%4,%5,%6,%7}, {%8,%9}, {%0,%1,%2,%3};"
        : "+f"(d[0]), "+f"(d[1]), "+f"(d[2]), "+f"(d[3])
        : "r"(a[0]), "r"(a[1]), "r"(a[2]), "r"(a[3]), "r"(b[0]), "r"(b[1]));
}

// pack two fp32 -> fp16x2 reg (lo = low half)
__device__ __forceinline__ uint32_t pack_f16(float lo, float hi) {
    uint32_t r;
    asm("cvt.rn.f16x2.f32 %0, %1, %2;" : "=r"(r) : "f"(hi), "f"(lo));
    return r;
}

// scale a fp16x2 reg by fp32 s (unpack -> fp32 mul -> repack; unbiased)
__device__ __forceinline__ uint32_t scale_h2(uint32_t v, float s) {
    __half2 h = *(__half2*)&v;
    float lo = __low2float(h) * s;
    float hi = __high2float(h) * s;
    return pack_f16(lo, hi);
}

__device__ __forceinline__ float ex2f(float x) {
    float r;
    asm("ex2.approx.f32 %0, %1;" : "=f"(r) : "f"(x));
    return r;
}

__device__ __forceinline__ uint32_t smem_u32(const void* p) {
    uint32_t a;
    asm("{ .reg .u64 t; cvta.to.shared.u64 t, %1; cvt.u32.u64 %0, t; }"
        : "=r"(a) : "l"(p));
    return a;
}

__device__ __forceinline__ void ldsm_x4(uint32_t* r, uint32_t addr) {
    asm volatile("ldmatrix.sync.aligned.m8n8.x4.shared.b16 {%0,%1,%2,%3}, [%4];"
                 : "=r"(r[0]), "=r"(r[1]), "=r"(r[2]), "=r"(r[3]) : "r"(addr));
}

__device__ __forceinline__ void ldsm_x4_trans(uint32_t* r, uint32_t addr) {
    asm volatile("ldmatrix.sync.aligned.m8n8.x4.trans.shared.b16 {%0,%1,%2,%3}, [%4];"
                 : "=r"(r[0]), "=r"(r[1]), "=r"(r[2]), "=r"(r[3]) : "r"(addr));
}

// fp16 (2-byte) fragment offsets, stride in halves.
// a mats: (mlo,klo),(mhi,klo),(mlo,khi),(mhi,khi); b mats: (nlo,klo),(nlo,khi),(nhi,klo),(nhi,khi)
__device__ __forceinline__ uint32_t a_frag_off16(int lane, int stride) {
    int mat = lane >> 3, rw = lane & 7;
    return (uint32_t)(((8 * (mat & 1) + rw) * stride + 8 * (mat >> 1)) * 2);
}
__device__ __forceinline__ uint32_t b_frag_off16(int lane, int stride) {
    int mat = lane >> 3, rw = lane & 7;
    return (uint32_t)(((8 * (mat >> 1) + rw) * stride + 8 * (mat & 1)) * 2);
}

#define CP16(s, g) \
    asm volatile("cp.async.cg.shared.global [%0], [%1], 16;" :: "r"(s), "l"(g) : "memory")
#define CP_COMMIT() asm volatile("cp.async.commit_group;" ::: "memory")
#define CP_WAIT(n)  asm volatile("cp.async.wait_group %0;" :: "n"(n) : "memory")

// ---------------------------------------------------------------------------
// x -> fp16 conversion (8 floats / thread, 16B stores)
// ---------------------------------------------------------------------------
__global__ __launch_bounds__(256) void cvt_kernel(const float* __restrict__ x)
{
    size_t i = ((size_t)blockIdx.x * 256 + threadIdx.x) * 8;
    float4 v0 = *(const float4*)(x + i);
    float4 v1 = *(const float4*)(x + i + 4);
    uint4 o;
    o.x = pack_f16(v0.x, v0.y);
    o.y = pack_f16(v0.z, v0.w);
    o.z = pack_f16(v1.x, v1.y);
    o.w = pack_f16(v1.z, v1.w);
    *(uint4*)(g_xh + i) = o;
}

// ---------------------------------------------------------------------------
// Weight transpose + fp16, both weights in one launch (z selects).
// src[K][N] fp32 -> g_wth(+off)[N][K] fp16. Tile 64k x 32n, block 256.
// ---------------------------------------------------------------------------
__global__ __launch_bounds__(256) void transpose_kernel(
    const float* __restrict__ w_attn, const float* __restrict__ w_proj)
{
    __shared__ __half st[32][72];
    const int sel = blockIdx.z;
    const int N = sel ? CDIM : 3 * CDIM;
    if (sel && blockIdx.x >= (unsigned)(CDIM / 32)) return;
    const float* src = sel ? w_proj : w_attn;
    __half* dst = g_wth + (sel ? (size_t)3 * CDIM * CDIM : 0);
    const int K = CDIM;
    const int nb = blockIdx.x * 32, kb = blockIdx.y * 64;
    const int tid = threadIdx.x;

#pragma unroll
    for (int it = 0; it < 2; it++) {
        const int f = tid + 256 * it;
        const int row = f >> 3;
        const int c4 = f & 7;
        float4 v = *(const float4*)(src + (size_t)(kb + row) * N + nb + c4 * 4);
        st[c4 * 4 + 0][row] = __float2half(v.x);
        st[c4 * 4 + 1][row] = __float2half(v.y);
        st[c4 * 4 + 2][row] = __float2half(v.z);
        st[c4 * 4 + 3][row] = __float2half(v.w);
    }
    __syncthreads();

    {
        const int n = tid >> 3;
        const int ch = tid & 7;
        uint4 v = *(const uint4*)&st[n][ch * 8];
        *(uint4*)(dst + (size_t)(nb + n) * K + kb + ch * 8) = v;
    }
}

// ---------------------------------------------------------------------------
// fp16 GEMM (m16n8k16), BK=64: 128x128 CTA tile, 256 threads = 8 warps
// (2m x 4n), warp tile 64x32 -> acc 64 regs/thread, <=128 total ->
// 2 CTAs/SM = 16 warps/SM. 2-stage cp.async ring (73,728 B).
// mode 0: A=g_xh, C=g_qkvh (fp16); mode 1: A=g_yh, C=C_param (fp32).
// ---------------------------------------------------------------------------
#define SH 72                        // smem stride (halves); 144B rows, LDSM conflict-free
#define HTILE_B (128 * SH * 2)       // 18432 per tile (A or B)
#define HSTAGE (2 * HTILE_B)         // 36864 per stage
#define HGSMEM (2 * HSTAGE)          // 73728

__global__ __launch_bounds__(256, 2) void gemm_h_kernel(
    const float* __restrict__ bias, float* __restrict__ C_param,
    int M, int N, int K, int mode)
{
    extern __shared__ char smh[];
    const __half* A  = mode ? g_yh : g_xh;
    const __half* Bt = g_wth + (mode ? (size_t)3 * CDIM * CDIM : 0);

    const int tid = threadIdx.x, lane = tid & 31, wid = tid >> 5;
    const int wm = wid >> 2, wn = wid & 3;
    const int g = lane >> 2, q = lane & 3;
    const int m0 = blockIdx.y * 128, n0 = blockIdx.x * 128;
    const uint32_t sb = smem_u32(smh);

    const uint32_t a_off = a_frag_off16(lane, SH);
    const uint32_t b_off = b_frag_off16(lane, SH);

    float acc[4][4][4];
#pragma unroll
    for (int mt = 0; mt < 4; mt++)
#pragma unroll
        for (int nt = 0; nt < 4; nt++)
#pragma unroll
            for (int e = 0; e < 4; e++) acc[mt][nt][e] = 0.f;

    const int nc = K / 64;

    // prefetch stages 0 and 1 (per stage: 128 rows x 8 chunks per operand)
#pragma unroll
    for (int s = 0; s < 2; s++) {
        const int k0 = s * 64;
        const uint32_t st = sb + (uint32_t)(s * HSTAGE);
#pragma unroll
        for (int i = 0; i < 4; i++) {
            const int f = tid + 256 * i;          // 0..1023
            const int row = f >> 3, c8 = f & 7;
            const uint32_t so = st + (uint32_t)(row * (SH * 2) + c8 * 16);
            CP16(so, A + (size_t)(m0 + row) * K + k0 + c8 * 8);
            CP16(so + HTILE_B, Bt + (size_t)(n0 + row) * K + k0 + c8 * 8);
        }
        CP_COMMIT();
    }

    for (int c = 0; c < nc; c++) {
        if (c == nc - 1) { CP_WAIT(0); } else { CP_WAIT(1); }
        __syncthreads();

        const uint32_t ab = sb + (uint32_t)((c & 1) * HSTAGE);
        const uint32_t bbse = ab + HTILE_B;
#pragma unroll
        for (int kk = 0; kk < 64; kk += 16) {
            uint32_t af[4][4], bf[2][4];
#pragma unroll
            for (int mt = 0; mt < 4; mt++)
                ldsm_x4(af[mt], ab + (uint32_t)(((wm * 64 + mt * 16) * SH + kk) * 2) + a_off);
#pragma unroll
            for (int pr = 0; pr < 2; pr++)
                ldsm_x4(bf[pr], bbse + (uint32_t)(((wn * 32 + pr * 16) * SH + kk) * 2) + b_off);
#pragma unroll
            for (int mt = 0; mt < 4; mt++)
#pragma unroll
                for (int nt = 0; nt < 4; nt++)
                    mma_f16(acc[mt][nt], af[mt], bf[nt >> 1] + (nt & 1) * 2);
        }
        __syncthreads();

        if (c + 2 < nc) {
            const int k0 = (c + 2) * 64;
            const uint32_t st = sb + (uint32_t)((c & 1) * HSTAGE);
#pragma unroll
            for (int i = 0; i < 4; i++) {
                const int f = tid + 256 * i;
                const int row = f >> 3, c8 = f & 7;
                const uint32_t so = st + (uint32_t)(row * (SH * 2) + c8 * 16);
                CP16(so, A + (size_t)(m0 + row) * K + k0 + c8 * 8);
                CP16(so + HTILE_B, Bt + (size_t)(n0 + row) * K + k0 + c8 * 8);
            }
            CP_COMMIT();
        }
    }

    // epilogue: bias (fp32), then fp16 store (mode 0 -> g_qkvh) or fp32 (mode 1)
#pragma unroll
    for (int mt = 0; mt < 4; mt++) {
        int r0 = m0 + wm * 64 + mt * 16 + g;
#pragma unroll
        for (int nt = 0; nt < 4; nt++) {
            int cc = n0 + wn * 32 + nt * 8 + 2 * q;
            float b0 = bias[cc], b1 = bias[cc + 1];
            float v00 = acc[mt][nt][0] + b0, v01 = acc[mt][nt][1] + b1;
            float v10 = acc[mt][nt][2] + b0, v11 = acc[mt][nt][3] + b1;
            if (mode == 0) {
                *(uint32_t*)(g_qkvh + (size_t)r0 * N + cc)       = pack_f16(v00, v01);
                *(uint32_t*)(g_qkvh + (size_t)(r0 + 8) * N + cc) = pack_f16(v10, v11);
            } else {
                *(float2*)(C_param + (size_t)r0 * N + cc)       = make_float2(v00, v01);
                *(float2*)(C_param + (size_t)(r0 + 8) * N + cc) = make_float2(v10, v11);
            }
        }
    }
}

// ---------------------------------------------------------------------------
// Flash attention (unchanged from R16): fp16 QK^T + fp16 PV, trans-V via
// ldmatrix.x4.trans on [key][d] tiles. 64-query tile, 128 threads = 4 warps,
// double-buffered K/V. Smem: K0|K1|V0|V1 = 36,864 B, 3 CTAs/SM.
// ---------------------------------------------------------------------------
#define AST 72
#define ATILE_B (64 * AST * 2)       // 9216
#define ASMEM (4 * ATILE_B)          // 36864

__global__ __launch_bounds__(128, 3) void attn_h_kernel()
{
    extern __shared__ char sma[];

    const int qt = (gridDim.x - 1) - blockIdx.x;   // heavy-first
    const int h = blockIdx.y, b = blockIdx.z;
    const int tid = threadIdx.x, lane = tid & 31, w = tid >> 5;
    const int g = lane >> 2, q = lane & 3;
    const int q0 = qt * 64;

    const uint32_t sb = smem_u32(sma);

    const size_t rs = 3 * CDIM;
    const __half* qb = g_qkvh + (size_t)b * TLEN * rs + h * DH;
    const __half* kb = qb + CDIM;
    const __half* vb = qb + 2 * CDIM;

    const uint32_t aoff = a_frag_off16(lane, AST);
    const uint32_t boff = b_frag_off16(lane, AST);
    const uint32_t vtoff = a_frag_off16(lane, AST);

    // ---- preload: Q -> K1 region; K tile 0 -> K0; V tile 0 -> V0 ----
    {
        const uint32_t sQ = sb + ATILE_B;
#pragma unroll
        for (int p = 0; p < 4; p++) {
            const int idx = tid + 128 * p;
            const int r = idx >> 3, c = idx & 7;
            const uint32_t ro = (uint32_t)(r * (AST * 2) + c * 16);
            CP16(sQ + ro, qb + (size_t)(q0 + r) * rs + c * 8);
            CP16(sb + ro, kb + (size_t)r * rs + c * 8);
            CP16(sb + 2 * ATILE_B + ro, vb + (size_t)r * rs + c * 8);
        }
        CP_COMMIT(); CP_WAIT(0);
    }
    __syncthreads();

    // hoist Q fragments (4 k16-chunks), scale by (1/8)*log2(e) in fp32
    const float QSCALE = 0.125f * 1.4426950408889634f;
    uint32_t qf[4][4];
#pragma unroll
    for (int kd = 0; kd < 4; kd++) {
        ldsm_x4(qf[kd], sb + ATILE_B + (uint32_t)(((w * 16) * AST + kd * 16) * 2) + aoff);
#pragma unroll
        for (int e = 0; e < 4; e++)
            qf[kd][e] = scale_h2(qf[kd][e], QSCALE);
    }

    float so[8][4];
    float mrow[2] = {-1e30f, -1e30f}, lsum[2] = {0.f, 0.f};
#pragma unroll
    for (int nt = 0; nt < 8; nt++)
#pragma unroll
        for (int e = 0; e < 4; e++) so[nt][e] = 0.f;

    for (int kt = 0; kt <= qt; kt++) {
        const int p = kt & 1;
        const uint32_t sK = sb + (uint32_t)(p * ATILE_B);
        const uint32_t sV = sb + (uint32_t)((2 + p) * ATILE_B);

        __syncthreads();   // barrier A

        if (kt < qt) {
            const uint32_t nK = sb + (uint32_t)((1 - p) * ATILE_B);
            const uint32_t nV = sb + (uint32_t)((2 + (1 - p)) * ATILE_B);
            const int k0r = (kt + 1) * 64;
#pragma unroll
            for (int pp = 0; pp < 4; pp++) {
                const int idx = tid + 128 * pp;
                const int r = idx >> 3, c = idx & 7;
                const uint32_t ro = (uint32_t)(r * (AST * 2) + c * 16);
                CP16(nK + ro, kb + (size_t)(k0r + r) * rs + c * 8);
                CP16(nV + ro, vb + (size_t)(k0r + r) * rs + c * 8);
            }
            CP_COMMIT();
            CP_WAIT(1);
        } else {
            CP_WAIT(0);
        }
        __syncthreads();    // barrier B

        // ---- S = Q K^T (fp16 m16n8k16, log2 domain) ----
        float sc[8][4];
#pragma unroll
        for (int nt = 0; nt < 8; nt++)
#pragma unroll
            for (int e = 0; e < 4; e++) sc[nt][e] = 0.f;

#pragma unroll
        for (int kd = 0; kd < 4; kd++) {
            uint32_t bf[4][4];
#pragma unroll
            for (int pr = 0; pr < 4; pr++)
                ldsm_x4(bf[pr], sK + (uint32_t)(((pr * 16) * AST + kd * 16) * 2) + boff);
#pragma unroll
            for (int nt = 0; nt < 8; nt++)
                mma_f16(sc[nt], qf[kd], bf[nt >> 1] + (nt & 1) * 2);
        }

        // ---- causal mask on diagonal tile ----
        if (kt == qt) {
            const int r0 = w * 16 + g, r1 = r0 + 8;
#pragma unroll
            for (int nt = 0; nt < 8; nt++) {
                const int c = nt * 8 + 2 * q;
                if (c     > r0) sc[nt][0] = -1e30f;
                if (c + 1 > r0) sc[nt][1] = -1e30f;
                if (c     > r1) sc[nt][2] = -1e30f;
                if (c + 1 > r1) sc[nt][3] = -1e30f;
            }
        }

        // ---- online softmax (base-2; 2 rows per thread) ----
        float mx0 = -1e30f, mx1 = -1e30f;
#pragma unroll
        for (int nt = 0; nt < 8; nt++) {
            mx0 = fmaxf(mx0, fmaxf(sc[nt][0], sc[nt][1]));
            mx1 = fmaxf(mx1, fmaxf(sc[nt][2], sc[nt][3]));
        }
        mx0 = fmaxf(mx0, __shfl_xor_sync(0xffffffffu, mx0, 1));
        mx0 = fmaxf(mx0, __shfl_xor_sync(0xffffffffu, mx0, 2));
        mx1 = fmaxf(mx1, __shfl_xor_sync(0xffffffffu, mx1, 1));
        mx1 = fmaxf(mx1, __shfl_xor_sync(0xffffffffu, mx1, 2));

        const float mn0 = fmaxf(mrow[0], mx0);
        const float mn1 = fmaxf(mrow[1], mx1);
        const float al0 = ex2f(mrow[0] - mn0);
        const float al1 = ex2f(mrow[1] - mn1);
        mrow[0] = mn0; mrow[1] = mn1;

        float s0 = 0.f, s1 = 0.f;
#pragma unroll
        for (int nt = 0; nt < 8; nt++) {
            sc[nt][0] = ex2f(sc[nt][0] - mn0); s0 += sc[nt][0];
            sc[nt][1] = ex2f(sc[nt][1] - mn0); s0 += sc[nt][1];
            sc[nt][2] = ex2f(sc[nt][2] - mn1); s1 += sc[nt][2];
            sc[nt][3] = ex2f(sc[nt][3] - mn1); s1 += sc[nt][3];
        }
        s0 += __shfl_xor_sync(0xffffffffu, s0, 1);
        s0 += __shfl_xor_sync(0xffffffffu, s0, 2);
        s1 += __shfl_xor_sync(0xffffffffu, s1, 1);
        s1 += __shfl_xor_sync(0xffffffffu, s1, 2);
        lsum[0] = lsum[0] * al0 + s0;
        lsum[1] = lsum[1] * al1 + s1;

#pragma unroll
        for (int nt = 0; nt < 8; nt++) {
            so[nt][0] *= al0; so[nt][1] *= al0;
            so[nt][2] *= al1; so[nt][3] *= al1;
        }

        // ---- pack P to fp16 a-frags in registers ----
        uint32_t pa[4][4];
#pragma unroll
        for (int kc = 0; kc < 4; kc++) {
            pa[kc][0] = pack_f16(sc[2 * kc][0],     sc[2 * kc][1]);
            pa[kc][1] = pack_f16(sc[2 * kc][2],     sc[2 * kc][3]);
            pa[kc][2] = pack_f16(sc[2 * kc + 1][0], sc[2 * kc + 1][1]);
            pa[kc][3] = pack_f16(sc[2 * kc + 1][2], sc[2 * kc + 1][3]);
        }

        // ---- O += P V : b-frags via ldmatrix.trans on [key][d] V tile ----
#pragma unroll
        for (int kc = 0; kc < 4; kc++) {
#pragma unroll
            for (int nt2 = 0; nt2 < 4; nt2++) {
                uint32_t bf[4];
                ldsm_x4_trans(bf, sV + (uint32_t)(((kc * 16) * AST + nt2 * 16) * 2) + vtoff);
                mma_f16(so[2 * nt2],     pa[kc], bf + 0);
                mma_f16(so[2 * nt2 + 1], pa[kc], bf + 2);
            }
        }
    }

    // ---- normalize + store y as fp16 (for fp16 GEMM2) ----
    {
        const float inv0 = 1.f / lsum[0];
        const float inv1 = 1.f / lsum[1];
        const int r0 = q0 + w * 16 + g;
        __half* yb = g_yh + (size_t)b * TLEN * CDIM + h * DH;
#pragma unroll
        for (int nt = 0; nt < 8; nt++) {
            const int c = nt * 8 + 2 * q;
            *(uint32_t*)(yb + (size_t)r0 * CDIM + c) =
                pack_f16(so[nt][0] * inv0, so[nt][1] * inv0);
            *(uint32_t*)(yb + (size_t)(r0 + 8) * CDIM + c) =
                pack_f16(so[nt][2] * inv1, so[nt][3] * inv1);
        }
    }
}

// ---------------------------------------------------------------------------
extern "C" void kernel_launch(void* const* d_in, const int* in_sizes, int n_in,
                              void* d_out, int out_size)
{
    const float* x      = (const float*)d_in[0];
    const float* W_attn = (const float*)d_in[1];
    const float* b_attn = (const float*)d_in[2];
    const float* W_proj = (const float*)d_in[3];
    const float* b_proj = (const float*)d_in[4];
    float* out = (float*)d_out;

    cudaFuncSetAttribute(gemm_h_kernel, cudaFuncAttributeMaxDynamicSharedMemorySize, HGSMEM);
    cudaFuncSetAttribute(attn_h_kernel, cudaFuncAttributeMaxDynamicSharedMemorySize, ASMEM);

    // 0) pre-convert x; transpose+convert both weights (one launch)
    cvt_kernel<<<(MROWS * CDIM) / (256 * 8), 256>>>(x);
    transpose_kernel<<<dim3((3 * CDIM) / 32, CDIM / 64, 2), 256>>>(W_attn, W_proj);

    // 1) qkv = x @ W_attn + b_attn (fp16 in/out, fp32 accum)
    {
        dim3 grid((3 * CDIM) / 128, MROWS / 128);
        gemm_h_kernel<<<grid, 256, HGSMEM>>>(b_attn, nullptr, MROWS, 3 * CDIM, CDIM, 0);
    }
    // 2) flash attention (fp16 QK + fp16 PV, trans-V) -> g_yh
    {
        dim3 grid(TLEN / 64, HN, BSZ);
        attn_h_kernel<<<grid, 128, ASMEM>>>();
    }
    // 3) out = y @ W_proj + b_proj (fp16 in, fp32 accum + store)
    {
        dim3 grid(CDIM / 128, MROWS / 128);
        gemm_h_kernel<<<grid, 256, HGSMEM>>>(b_proj, out, MROWS, CDIM, CDIM, 1);
    }
}